// round 16
// baseline (speedup 1.0000x reference)
#include <cuda_runtime.h>
#include <cuda_fp16.h>
#include <cstdint>

#define B_ 64
#define N_ 197
#define C_ 768
#define H_ 12
#define DH_ 64
#define M_ (B_*N_)          // 12608
#define NN_ (N_*N_)         // 38809
#define NUM_REL_ 732
#define QSCALE 0.125f
#define KP_ 1536            // packed K = 2*768 (2-term fp16 split)
#define NCH_ 24             // K chunks of 64 fp16
#define SROW 72             // gemm smem row stride in fp16 (64 + 8 pad)
#define SA_ (128*SROW*2)    // one smem tile: 18432 bytes
#define SKP 136             // scores smem row stride in fp16 (128 + 8 pad)
#define MP_ 224             // padded token rows for scores (rows >=197 stay zero)

// ---------------- scratch ----------------
__device__ float g_v[(size_t)B_*H_*N_*DH_];
__device__ __half g_qp[(size_t)B_*H_*MP_*128];   // q packed [hi(d), lo(d)], QSCALE folded
__device__ __half g_kp[(size_t)B_*H_*MP_*128];   // k packed [hi(d), hi(d)]
__device__ float g_attn [(size_t)B_*H_*NN_];
__device__ float g_attn2[(size_t)B_*H_*NN_];
__device__ __half g_apack[(size_t)M_*KP_];       // packed activations [hi, lo]
__device__ __half g_bqkv [(size_t)3*C_*KP_];     // packed qkv weights [hi, hi]
__device__ __half g_bproj[(size_t)C_*KP_];       // packed proj weights [hi, hi]

// ---------------- PTX helpers (baseline ISA only) ----------------
__device__ __forceinline__ uint32_t smem_to_u32(const void* p) {
    uint32_t a;
    asm("{ .reg .u64 t; cvta.to.shared.u64 t, %1; cvt.u32.u64 %0, t; }" : "=r"(a) : "l"(p));
    return a;
}
#define CP_ASYNC16(sm, gp) \
    asm volatile("cp.async.cg.shared.global [%0], [%1], 16;" :: "r"(sm), "l"(gp))
#define CP_COMMIT()  asm volatile("cp.async.commit_group;" ::: "memory")
#define CP_WAIT0()   asm volatile("cp.async.wait_group 0;" ::: "memory")
#define LDSM_X4(r0,r1,r2,r3, addr) \
    asm volatile("ldmatrix.sync.aligned.m8n8.x4.shared.b16 {%0,%1,%2,%3}, [%4];" \
        : "=r"(r0), "=r"(r1), "=r"(r2), "=r"(r3) : "r"(addr))

__device__ __forceinline__ void mma16816(float* c, const uint32_t* a, uint32_t b0, uint32_t b1) {
    asm volatile("mma.sync.aligned.m16n8k16.row.col.f32.f16.f16.f32 "
        "{%0,%1,%2,%3}, {%4,%5,%6,%7}, {%8,%9}, {%0,%1,%2,%3};"
        : "+f"(c[0]), "+f"(c[1]), "+f"(c[2]), "+f"(c[3])
        : "r"(a[0]), "r"(a[1]), "r"(a[2]), "r"(a[3]), "r"(b0), "r"(b1));
}

// =====================================================================
// Pack kernels: f32 -> 2-term fp16 split along packed K (KP_ = 2*C)
// =====================================================================
__global__ __launch_bounds__(256) void pack_a(const float* __restrict__ src,
                                              __half* __restrict__ dst, int total)
{
    int idx = blockIdx.x * 256 + threadIdx.x;
    if (idx >= total) return;
    int row = idx / C_, k = idx - row * C_;
    float v = src[idx];
    __half hi = __float2half(v);
    __half lo = __float2half(v - __half2float(hi));
    size_t ro = (size_t)row * KP_;
    dst[ro + k] = hi; dst[ro + C_ + k] = lo;
}
__global__ __launch_bounds__(256) void pack_b(const float* __restrict__ src,
                                              __half* __restrict__ dst, int total)
{
    int idx = blockIdx.x * 256 + threadIdx.x;
    if (idx >= total) return;
    int row = idx / C_, k = idx - row * C_;
    __half hi = __float2half(src[idx]);
    size_t ro = (size_t)row * KP_;
    dst[ro + k] = hi; dst[ro + C_ + k] = hi;
}

// =====================================================================
// mma.sync GEMM (proven shape): block 128x128, 8 warps (2Mx4N),
// warp tile 64x32, BK=64, double-buffered cp.async, 2 CTAs/SM.
// MODE 0: qkv epilogue (q,k -> packed fp16; v -> f32); MODE 1: proj -> out.
// =====================================================================
template<int MODE>
__global__ __launch_bounds__(256) void tc_gemm(
    const __half* __restrict__ Ap, const __half* __restrict__ Bp,
    const float* __restrict__ p_qb, const float* __restrict__ p_vb,
    const float* __restrict__ sscale, const float* __restrict__ sshift,
    float* __restrict__ outp)
{
    extern __shared__ char smem_raw[];
    const uint32_t sbase = smem_to_u32(smem_raw);
    const int tid = threadIdx.x;
    const int lane = tid & 31, wid = tid >> 5;
    const int wm = wid & 1;
    const int wn = wid >> 1;
    const int row0 = blockIdx.x * 128;
    const int col0 = blockIdx.y * 128;

    const int lcol = tid & 7;
    const int lrow = tid >> 3;
    const __half* agp[4];
    const __half* bgp[4];
#pragma unroll
    for (int u = 0; u < 4; u++) {
        int ar = min(row0 + lrow + u * 32, M_ - 1);
        agp[u] = Ap + (size_t)ar * KP_ + lcol * 8;
        bgp[u] = Bp + (size_t)(col0 + lrow + u * 32) * KP_ + lcol * 8;
    }
    const uint32_t ssto = (uint32_t)((lrow * SROW + lcol * 8) * 2);

    auto load_chunk = [&](int ch, int bsel) {
        const uint32_t abuf = sbase + bsel * SA_;
        const uint32_t bbuf = sbase + 2 * SA_ + bsel * SA_;
        const int ko = ch * 64;
#pragma unroll
        for (int u = 0; u < 4; u++) {
            CP_ASYNC16(abuf + ssto + u * 32 * SROW * 2, agp[u] + ko);
            CP_ASYNC16(bbuf + ssto + u * 32 * SROW * 2, bgp[u] + ko);
        }
        CP_COMMIT();
    };

    const uint32_t a_l = ((wm * 64 + (lane & 15)) * SROW + (lane >> 4) * 8) * 2;
    const uint32_t b_l = ((wn * 32 + (lane & 15)) * SROW + (lane >> 4) * 8) * 2;

    float acc[4][4][4];
#pragma unroll
    for (int i = 0; i < 4; i++)
#pragma unroll
        for (int j = 0; j < 4; j++)
#pragma unroll
            for (int r = 0; r < 4; r++) acc[i][j][r] = 0.f;

    load_chunk(0, 0);
    CP_WAIT0();
    __syncthreads();

    for (int ch = 0; ch < NCH_; ch++) {
        const int bsel = ch & 1;
        if (ch + 1 < NCH_) load_chunk(ch + 1, bsel ^ 1);

        const uint32_t abuf = sbase + bsel * SA_;
        const uint32_t bbuf = sbase + 2 * SA_ + bsel * SA_;
#pragma unroll
        for (int ks = 0; ks < 64; ks += 16) {
            uint32_t a[4][4];
#pragma unroll
            for (int mf = 0; mf < 4; mf++)
                LDSM_X4(a[mf][0], a[mf][1], a[mf][2], a[mf][3],
                        abuf + a_l + (mf * 16 * SROW + ks) * 2);
            uint32_t bq[2][4];
#pragma unroll
            for (int nf2 = 0; nf2 < 2; nf2++)
                LDSM_X4(bq[nf2][0], bq[nf2][1], bq[nf2][2], bq[nf2][3],
                        bbuf + b_l + (nf2 * 16 * SROW + ks) * 2);
#pragma unroll
            for (int mf = 0; mf < 4; mf++) {
#pragma unroll
                for (int nf = 0; nf < 4; nf++) {
                    const int h2 = nf >> 1, odd = nf & 1;
                    mma16816(acc[mf][nf], a[mf], bq[h2][odd], bq[h2][odd + 2]);
                }
            }
        }
        CP_WAIT0();
        __syncthreads();
    }

    // ---- epilogue ----
    const int rbase = row0 + wm * 64 + (lane >> 2);
    const int cbase = col0 + wn * 32 + (lane & 3) * 2;
#pragma unroll
    for (int mf = 0; mf < 4; mf++) {
#pragma unroll
        for (int half = 0; half < 2; half++) {
            const int m = rbase + mf * 16 + half * 8;
            if (m >= M_) continue;
            const int bi = m / N_, t = m - bi * N_;
#pragma unroll
            for (int nf = 0; nf < 4; nf++) {
                float v0 = acc[mf][nf][half * 2 + 0];
                float v1 = acc[mf][nf][half * 2 + 1];
                const int n0 = cbase + nf * 8;
                if (MODE == 0) {
                    const int which = col0 / C_;          // uniform per block
#pragma unroll
                    for (int j = 0; j < 2; j++) {
                        int nn = n0 + j;
                        int rem = nn - which * C_;
                        int h = rem >> 6, d = rem & 63;
                        float bias = (which == 0) ? p_qb[rem] : ((which == 2) ? p_vb[rem] : 0.f);
                        float val = ((j ? v1 : v0) + bias) * sscale[nn] + sshift[nn];
                        if (which == 0) {
                            float qv = val * QSCALE;
                            __half hi = __float2half(qv);
                            __half lo = __float2half(qv - __half2float(hi));
                            size_t off = ((size_t)(bi * H_ + h) * MP_ + t) * 128 + d;
                            g_qp[off] = hi; g_qp[off + 64] = lo;
                        } else if (which == 1) {
                            __half hi = __float2half(val);
                            size_t off = ((size_t)(bi * H_ + h) * MP_ + t) * 128 + d;
                            g_kp[off] = hi; g_kp[off + 64] = hi;
                        } else {
                            g_v[(((size_t)(bi * H_ + h)) * N_ + t) * DH_ + d] = val;
                        }
                    }
                } else {
                    float* op = outp + (size_t)m * C_ + n0;
                    op[0] = (v0 + p_qb[n0])     * sscale[n0]     + sshift[n0];
                    op[1] = (v1 + p_qb[n0 + 1]) * sscale[n0 + 1] + sshift[n0 + 1];
                }
            }
        }
    }
}

// =====================================================================
// Kernel: attn[b,h] = softmax(q @ k^T + rel_bias) on TENSOR CORES.
// grid (2, B*H): blockIdx.x selects 112-row half; 256 threads; warps 0-6
// each own a 16x224 output tile (14 col-frags), K=128 fp16 (2-term split).
// Fused bias gather + in-register row softmax (shfl over 4-lane group).
// Stores are SCALAR (N=197 odd -> row base parity varies; no STG.64).
// =====================================================================
__global__ __launch_bounds__(256) void scores_tc(
    const float* __restrict__ rel_table, const int* __restrict__ rel_index)
{
    extern __shared__ char smraw[];
    const uint32_t sb = smem_to_u32(smraw);
    __half* kkp = (__half*)smraw;                  // [224][SKP]
    __half* qqp = kkp + MP_ * SKP;                 // [112][SKP]
    float*  tbl = (float*)(qqp + 112 * SKP);       // [732]
    const uint32_t kk_off = 0;
    const uint32_t qq_off = MP_ * SKP * 2;

    const int tid = threadIdx.x;
    const int mtile = blockIdx.x;                  // 0 or 1
    const int bh = blockIdx.y;
    const int h = bh % H_;
    const int rowbase = mtile * 112;

    const __half* kg = g_kp + (size_t)bh * MP_ * 128;
    const __half* qg = g_qp + (size_t)bh * MP_ * 128 + (size_t)rowbase * 128;

    // fill smem (uint4 = 8 fp16; 16 chunks per 128-elem row)
    for (int i = tid; i < MP_ * 16; i += 256) {
        int r = i >> 4, c = i & 15;
        *(uint4*)&kkp[r * SKP + c * 8] = ((const uint4*)kg)[i];
    }
    for (int i = tid; i < 112 * 16; i += 256) {
        int r = i >> 4, c = i & 15;
        *(uint4*)&qqp[r * SKP + c * 8] = ((const uint4*)qg)[i];
    }
    for (int i = tid; i < NUM_REL_; i += 256) tbl[i] = rel_table[i * H_ + h];
    __syncthreads();

    const int wid = tid >> 5, lane = tid & 31;
    if (wid >= 7) return;

    float acc[14][2][4];
#pragma unroll
    for (int ct = 0; ct < 14; ct++)
#pragma unroll
        for (int hf = 0; hf < 2; hf++)
#pragma unroll
            for (int r = 0; r < 4; r++) acc[ct][hf][r] = 0.f;

    const uint32_t a_l = sb + qq_off + ((wid * 16 + (lane & 15)) * SKP + (lane >> 4) * 8) * 2;
    const uint32_t b_l = sb + kk_off + (((lane & 15)) * SKP + (lane >> 4) * 8) * 2;

#pragma unroll
    for (int ks = 0; ks < 128; ks += 16) {
        uint32_t a[4];
        LDSM_X4(a[0], a[1], a[2], a[3], a_l + ks * 2);
#pragma unroll
        for (int ct = 0; ct < 14; ct++) {
            uint32_t bq[4];
            LDSM_X4(bq[0], bq[1], bq[2], bq[3], b_l + (ct * 16 * SKP + ks) * 2);
            mma16816(acc[ct][0], a, bq[0], bq[2]);
            mma16816(acc[ct][1], a, bq[1], bq[3]);
        }
    }

    // ---- fused bias + softmax + store (per row; 4 lanes share a row) ----
    float* outp = g_attn + (size_t)bh * NN_;
    const int rb = rowbase + wid * 16 + (lane >> 2);
#pragma unroll
    for (int hr = 0; hr < 2; hr++) {
        const int n = rb + hr * 8;
        const int nc = min(n, N_ - 1);
        const int* ridx = rel_index + nc * N_;
        float mx = -1e30f;
#pragma unroll
        for (int ct = 0; ct < 14; ct++)
#pragma unroll
            for (int hf = 0; hf < 2; hf++)
#pragma unroll
                for (int j = 0; j < 2; j++) {
                    int mm = ct * 16 + hf * 8 + (lane & 3) * 2 + j;
                    float v = acc[ct][hf][hr * 2 + j];
                    v = (mm < N_) ? v + tbl[ridx[mm]] : -1e30f;
                    acc[ct][hf][hr * 2 + j] = v;
                    mx = fmaxf(mx, v);
                }
        mx = fmaxf(mx, __shfl_xor_sync(0xffffffffu, mx, 1));
        mx = fmaxf(mx, __shfl_xor_sync(0xffffffffu, mx, 2));
        float sum = 0.f;
#pragma unroll
        for (int ct = 0; ct < 14; ct++)
#pragma unroll
            for (int hf = 0; hf < 2; hf++)
#pragma unroll
                for (int j = 0; j < 2; j++) {
                    float e = __expf(acc[ct][hf][hr * 2 + j] - mx);
                    acc[ct][hf][hr * 2 + j] = e;
                    sum += e;
                }
        sum += __shfl_xor_sync(0xffffffffu, sum, 1);
        sum += __shfl_xor_sync(0xffffffffu, sum, 2);
        const float inv = 1.f / sum;
        if (n < N_) {
            float* rowp = outp + (size_t)n * N_;
#pragma unroll
            for (int ct = 0; ct < 14; ct++)
#pragma unroll
                for (int hf = 0; hf < 2; hf++) {
                    int mm = ct * 16 + hf * 8 + (lane & 3) * 2;
                    if (mm < N_)     rowp[mm]     = acc[ct][hf][hr * 2 + 0] * inv;
                    if (mm + 1 < N_) rowp[mm + 1] = acc[ct][hf][hr * 2 + 1] * inv;
                }
        }
    }
}

// =====================================================================
// Kernel: DCF head mix -> f32 g_attn2
// =====================================================================
__global__ __launch_bounds__(256) void mix_kernel(const float* __restrict__ coeff)
{
    __shared__ float mixs[12][13];
    const int tid = threadIdx.x;
    if (tid < 144) {
        int k = tid / 12, h = tid % 12;
        mixs[h][k] = coeff[k * 12 + h] + ((h == k) ? 1.f : 0.f);
    }
    __syncthreads();

    const int b = blockIdx.y;
    const int idx = blockIdx.x * 256 + tid;
    if (idx >= NN_) return;
    const float* ap = g_attn + (size_t)b * H_ * NN_ + idx;
    float a[12];
#pragma unroll
    for (int h = 0; h < 12; h++) a[h] = ap[(size_t)h * NN_];
    float* op = g_attn2 + (size_t)b * H_ * NN_ + idx;
#pragma unroll
    for (int k = 0; k < 12; k++) {
        float s = 0.f;
#pragma unroll
        for (int h = 0; h < 12; h++) s = fmaf(a[h], mixs[h][k], s);
        op[(size_t)k * NN_] = s;
    }
}

// =====================================================================
// Kernel: ctx = attn2 @ v (fp32, proven 64x64 tile). Epilogue writes
// ctx directly as 2-term fp16 split into g_apack [hi, lo].
// =====================================================================
__global__ __launch_bounds__(256) void av_gemm()
{
    __shared__ __align__(16) float As[16][68];
    __shared__ __align__(16) float Vs[16][68];
    const int tid = threadIdx.x;
    const int bh = blockIdx.y;
    const int row0 = blockIdx.x * 64;
    const float* A = g_attn2 + (size_t)bh * NN_;
    const float* V = g_v + (size_t)bh * N_ * DH_;
    const int tx = tid & 15, ty = tid >> 4;
    const int vr = tid >> 4;
    const int vc = (tid & 15) << 2;

    float acc[4][4];
#pragma unroll
    for (int i = 0; i < 4; i++)
#pragma unroll
        for (int j = 0; j < 4; j++) acc[i][j] = 0.f;

    for (int k0 = 0; k0 < N_; k0 += 16) {
#pragma unroll
        for (int u = 0; u < 4; u++) {
            int idx = tid + u * 256;
            int r = idx >> 4, kc = idx & 15;
            int n = row0 + r, k = k0 + kc;
            As[kc][r] = (n < N_ && k < N_) ? A[(size_t)n * N_ + k] : 0.f;
        }
        {
            int k = k0 + vr;
            float4 vv = (k < N_) ? *(const float4*)(V + (size_t)k * DH_ + vc)
                                 : make_float4(0.f, 0.f, 0.f, 0.f);
            *(float4*)&Vs[vr][vc] = vv;
        }
        __syncthreads();
#pragma unroll
        for (int kk = 0; kk < 16; kk++) {
            float4 av = *(const float4*)&As[kk][ty << 2];
            float4 bv = *(const float4*)&Vs[kk][tx << 2];
            float aa[4] = {av.x, av.y, av.z, av.w};
            float bb[4] = {bv.x, bv.y, bv.z, bv.w};
#pragma unroll
            for (int i = 0; i < 4; i++)
#pragma unroll
                for (int j = 0; j < 4; j++)
                    acc[i][j] = fmaf(aa[i], bb[j], acc[i][j]);
        }
        __syncthreads();
    }

    const int b = bh / H_, h = bh - b * H_;
#pragma unroll
    for (int i = 0; i < 4; i++) {
        int n = row0 + (ty << 2) + i;
        if (n < N_) {
            const size_t mrow = (size_t)(b * N_ + n) * KP_;
            const int c0 = h * DH_ + (tx << 2);
#pragma unroll
            for (int j = 0; j < 4; j++) {
                float val = acc[i][j];
                __half hi = __float2half(val);
                __half lo = __float2half(val - __half2float(hi));
                int c = c0 + j;
                g_apack[mrow + c]       = hi;
                g_apack[mrow + C_ + c]  = lo;
            }
        }
    }
}

// =====================================================================
// Host launcher
// =====================================================================
extern "C" void kernel_launch(void* const* d_in, const int* in_sizes, int n_in,
                              void* d_out, int out_size)
{
    const float* x         = (const float*)d_in[0];
    const float* qkv_w     = (const float*)d_in[1];
    const float* q_bias    = (const float*)d_in[2];
    const float* v_bias    = (const float*)d_in[3];
    const float* ss_qkv    = (const float*)d_in[4];
    const float* sh_qkv    = (const float*)d_in[5];
    const float* rel_table = (const float*)d_in[6];
    const float* coeff     = (const float*)d_in[7];
    const float* proj_w    = (const float*)d_in[8];
    const float* proj_b    = (const float*)d_in[9];
    const float* ss_proj   = (const float*)d_in[10];
    const float* sh_proj   = (const float*)d_in[11];
    const int*   rel_index = (const int*)d_in[12];
    float* out = (float*)d_out;

    const int gemm_smem = 4 * SA_;                                  // 73728
    cudaFuncSetAttribute(tc_gemm<0>, cudaFuncAttributeMaxDynamicSharedMemorySize, gemm_smem);
    cudaFuncSetAttribute(tc_gemm<1>, cudaFuncAttributeMaxDynamicSharedMemorySize, gemm_smem);
    const int scores_smem = (MP_ * SKP + 112 * SKP) * 2 + NUM_REL_ * 4;   // 94320
    cudaFuncSetAttribute(scores_tc, cudaFuncAttributeMaxDynamicSharedMemorySize, scores_smem);

    __half *apack, *bqkv, *bproj;
    cudaGetSymbolAddress((void**)&apack, g_apack);
    cudaGetSymbolAddress((void**)&bqkv,  g_bqkv);
    cudaGetSymbolAddress((void**)&bproj, g_bproj);

    // 1) pack x and weights -> 2-term fp16 split
    pack_a<<<(M_ * C_ + 255) / 256, 256>>>(x, apack, M_ * C_);
    pack_b<<<(3 * C_ * C_ + 255) / 256, 256>>>(qkv_w, bqkv, 3 * C_ * C_);
    pack_b<<<(C_ * C_ + 255) / 256, 256>>>(proj_w, bproj, C_ * C_);
    // 2) qkv GEMM + bias/SSF -> q,k packed fp16; v f32
    tc_gemm<0><<<dim3(99, 18), 256, gemm_smem>>>(apack, bqkv, q_bias, v_bias,
                                                 ss_qkv, sh_qkv, nullptr);
    // 3) scores + softmax on tensor cores
    scores_tc<<<dim3(2, B_ * H_), 256, scores_smem>>>(rel_table, rel_index);
    // 4) head mix (f32)
    mix_kernel<<<dim3((NN_ + 255) / 256, B_), 256>>>(coeff);
    // 5) attn2 @ v -> packed ctx directly into g_apack
    av_gemm<<<dim3(4, B_ * H_), 256>>>();
    // 6) proj GEMM
    tc_gemm<1><<<dim3(99, 6), 256, gemm_smem>>>(apack, bproj, proj_b, nullptr,
                                                ss_proj, sh_proj, out);
}